// round 6
// baseline (speedup 1.0000x reference)
#include <cuda_runtime.h>

#define Bn 4
#define Ln 200
#define Hn 256
#define NHn 4
#define HSn 64
#define Mrows (Bn * Ln)        // 800

__device__ float4 g_Q4 [Bn * Ln * (Hn / 4)];
__device__ float4 g_Kc4[Bn * Ln * (Hn / 4)];
__device__ float4 g_Vc4[Bn * Ln * (Hn / 4)];

__device__ __forceinline__ void fma2(unsigned long long& acc,
                                     unsigned long long a,
                                     unsigned long long b)
{
    asm("fma.rn.f32x2 %0, %1, %2, %0;" : "+l"(acc) : "l"(a), "l"(b));
}

// ---------------------------------------------------------------------------
// Tiled SGEMM projection with packed f32x2 FMA.
// Grid (13, 4, 3): 64x64 tiles; z selects {Q, Kc, Vc}. 256 thr = 16x16 of 4x4.
// W staged DUPLICATED in smem so LDS directly yields packed (w,w) operands.
// Register-prefetch double buffering hides per-chunk LDG latency.
// ---------------------------------------------------------------------------
#define XPITCH 68
#define WPW 136   // 128 dup floats + pad; row stride 544B (16B-aligned)

__global__ __launch_bounds__(256)
void proj_sgemm(const float4* __restrict__ queries,
                const float4* __restrict__ keys,
                const float4* __restrict__ apK4,
                const float4* __restrict__ apV4,
                const float4* __restrict__ Qw4, const float* __restrict__ Qb,
                const float4* __restrict__ Kw4, const float* __restrict__ Kb,
                const float4* __restrict__ Vw4, const float* __restrict__ Vb)
{
    __shared__ alignas(16) float xs [16][XPITCH];  // xs[kk][row]
    __shared__ alignas(16) float wsd[16][WPW];     // wsd[kk][2j],[2j+1] = w_j dup

    const int z   = blockIdx.z;
    const int rm0 = blockIdx.x * 64;
    const int cn0 = blockIdx.y * 64;

    const float4* __restrict__ X  = (z == 0) ? queries : keys;
    const float4* __restrict__ W  = (z == 0) ? Qw4 : (z == 1) ? Kw4 : Vw4;
    const float*  __restrict__ Bv = (z == 0) ? Qb : (z == 1) ? Kb : Vb;

    const int t    = threadIdx.x;
    const int tx   = t & 15;
    const int ty   = t >> 4;
    const int lrow = t >> 2;
    const int lq   = t & 3;

    // acc[p][j]: packed f32x2 over rows (4ty+2p, 4ty+2p+1), col tx*4+j
    unsigned long long acc[2][4];
    #pragma unroll
    for (int p = 0; p < 2; ++p)
        #pragma unroll
        for (int j = 0; j < 4; ++j) acc[p][j] = 0ULL;   // (0.f, 0.f)

    const int xr = min(rm0 + lrow, Mrows - 1);
    const int wc = cn0 + lrow;

    float4 xv = X[xr * (Hn / 4) + lq];
    float4 wv = W[wc * (Hn / 4) + lq];

    for (int k0 = 0; k0 < Hn; k0 += 16) {
        // stage current chunk
        xs[lq * 4 + 0][lrow] = xv.x;
        xs[lq * 4 + 1][lrow] = xv.y;
        xs[lq * 4 + 2][lrow] = xv.z;
        xs[lq * 4 + 3][lrow] = xv.w;
        {
            float2 d;
            d.x = wv.x; d.y = wv.x; *reinterpret_cast<float2*>(&wsd[lq*4+0][2*lrow]) = d;
            d.x = wv.y; d.y = wv.y; *reinterpret_cast<float2*>(&wsd[lq*4+1][2*lrow]) = d;
            d.x = wv.z; d.y = wv.z; *reinterpret_cast<float2*>(&wsd[lq*4+2][2*lrow]) = d;
            d.x = wv.w; d.y = wv.w; *reinterpret_cast<float2*>(&wsd[lq*4+3][2*lrow]) = d;
        }
        __syncthreads();

        // prefetch next chunk while computing
        if (k0 + 16 < Hn) {
            xv = X[xr * (Hn / 4) + ((k0 + 16) >> 2) + lq];
            wv = W[wc * (Hn / 4) + ((k0 + 16) >> 2) + lq];
        }

        #pragma unroll
        for (int kk = 0; kk < 16; ++kk) {
            const unsigned long long a0 =
                *reinterpret_cast<const unsigned long long*>(&xs[kk][ty * 4]);
            const unsigned long long a1 =
                *reinterpret_cast<const unsigned long long*>(&xs[kk][ty * 4 + 2]);
            const ulonglong2 w01 =
                *reinterpret_cast<const ulonglong2*>(&wsd[kk][8 * tx]);
            const ulonglong2 w23 =
                *reinterpret_cast<const ulonglong2*>(&wsd[kk][8 * tx + 4]);
            fma2(acc[0][0], a0, w01.x); fma2(acc[0][1], a0, w01.y);
            fma2(acc[0][2], a0, w23.x); fma2(acc[0][3], a0, w23.y);
            fma2(acc[1][0], a1, w01.x); fma2(acc[1][1], a1, w01.y);
            fma2(acc[1][2], a1, w23.x); fma2(acc[1][3], a1, w23.y);
        }
        __syncthreads();
    }

    // epilogue: bias (+abs_pos for K/V)
    const int colBase = cn0 + tx * 4;
    const float4 bias = *reinterpret_cast<const float4*>(&Bv[colBase]);
    float4* __restrict__ dst = (z == 0) ? g_Q4 : (z == 1) ? g_Kc4 : g_Vc4;
    const float4* __restrict__ ap = (z == 1) ? apK4 : apV4;

    #pragma unroll
    for (int p = 0; p < 2; ++p) {
        float2 c0 = *reinterpret_cast<float2*>(&acc[p][0]);
        float2 c1 = *reinterpret_cast<float2*>(&acc[p][1]);
        float2 c2 = *reinterpret_cast<float2*>(&acc[p][2]);
        float2 c3 = *reinterpret_cast<float2*>(&acc[p][3]);
        #pragma unroll
        for (int h = 0; h < 2; ++h) {           // h=0: lo lane (row 4ty+2p), h=1: hi
            const int row = rm0 + ty * 4 + 2 * p + h;
            if (row < Mrows) {
                float4 o;
                o.x = (h ? c0.y : c0.x) + bias.x;
                o.y = (h ? c1.y : c1.x) + bias.y;
                o.z = (h ? c2.y : c2.x) + bias.z;
                o.w = (h ? c3.y : c3.x) + bias.w;
                if (z != 0) {
                    const float4 pa = ap[row * (Hn / 4) + (colBase >> 2)];
                    o.x += pa.x; o.y += pa.y; o.z += pa.z; o.w += pa.w;
                }
                dst[row * (Hn / 4) + (colBase >> 2)] = o;
            }
        }
    }
}

// ---------------------------------------------------------------------------
// Attention (R5 structure, q loaded directly via LDG instead of smem staging).
// One CTA per (b, row-pair), 512 threads = 8 key-rows x 64 float4 lanes.
// ---------------------------------------------------------------------------
__global__ __launch_bounds__(512)
void attn_kernel(const float4* __restrict__ tK, const float4* __restrict__ tV,
                 const float4* __restrict__ dK, const float4* __restrict__ dV,
                 const unsigned char* __restrict__ time_mask,
                 float4* __restrict__ out)
{
    const int bx = blockIdx.x;               // 0..399
    const int b  = bx & (Bn - 1);
    const int p  = bx >> 2;                  // 0..99
    const int t    = threadIdx.x;
    const int msub = t >> 6;                 // 0..7
    const int qd   = t & 63;
    const int head = qd >> 4;

    __shared__ float  sW[NHn][Ln];
    __shared__ float4 sRed[8][64];

    const float4* __restrict__ Kc4 = g_Kc4;
    const float4* __restrict__ Vc4 = g_Vc4;
    const float4* __restrict__ gQ4 = g_Q4;

    #pragma unroll 1
    for (int rr = 0; rr < 2; ++rr) {
        const int l = rr ? p : (Ln - 1 - p);   // heavy row first

        const float4 qv = gQ4[(size_t)(b * Ln + l) * 64 + qd];

        const bool tm   = time_mask[b * Ln + l] != 0;
        const int  mEnd = tm ? Ln : (l + 1);
        const size_t rowBase = ((size_t)(b * Ln + l)) * Ln;

        if (!tm) {
            #pragma unroll 2
            for (int m0 = 0; m0 < mEnd; m0 += 8) {
                const int m = m0 + msub;
                float s = 0.f;
                if (m < mEnd) {
                    const size_t off = (rowBase + (size_t)m) * 64 + qd;
                    const float4 a = tK[off];
                    const float4 c = dK[off];
                    const float4 k = Kc4[(size_t)(b * Ln + m) * 64 + qd];
                    s = qv.x * (a.x + c.x + k.x) + qv.y * (a.y + c.y + k.y)
                      + qv.z * (a.z + c.z + k.z) + qv.w * (a.w + c.w + k.w);
                }
                s += __shfl_xor_sync(0xffffffffu, s, 8);
                s += __shfl_xor_sync(0xffffffffu, s, 4);
                s += __shfl_xor_sync(0xffffffffu, s, 2);
                s += __shfl_xor_sync(0xffffffffu, s, 1);
                if (m < mEnd && (qd & 15) == 0)
                    sW[head][m] = s;
            }
            __syncthreads();

            if (t < 128) {
                const int h    = t >> 5;
                const int lane = t & 31;
                float mx = -3.4e38f;
                for (int m = lane; m < mEnd; m += 32) mx = fmaxf(mx, sW[h][m]);
                #pragma unroll
                for (int o = 16; o; o >>= 1) mx = fmaxf(mx, __shfl_xor_sync(0xffffffffu, mx, o));
                float sum = 0.f;
                for (int m = lane; m < mEnd; m += 32) {
                    const float e = __expf(0.125f * (sW[h][m] - mx));  // 1/sqrt(64)
                    sW[h][m] = e;
                    sum += e;
                }
                #pragma unroll
                for (int o = 16; o; o >>= 1) sum += __shfl_xor_sync(0xffffffffu, sum, o);
                const float inv = 1.f / sum;
                for (int m = lane; m < mEnd; m += 32) sW[h][m] *= inv;
            }
        } else {
            const float u = 1.f / (float)Ln;
            for (int m = t; m < Ln; m += 512) {
                sW[0][m] = u; sW[1][m] = u; sW[2][m] = u; sW[3][m] = u;
            }
        }
        __syncthreads();

        float4 acc = make_float4(0.f, 0.f, 0.f, 0.f);
        #pragma unroll 2
        for (int m0 = 0; m0 < mEnd; m0 += 8) {
            const int m = m0 + msub;
            if (m < mEnd) {
                const float  a   = sW[head][m];
                const size_t off = (rowBase + (size_t)m) * 64 + qd;
                const float4 x = tV[off];
                const float4 y = dV[off];
                const float4 v = Vc4[(size_t)(b * Ln + m) * 64 + qd];
                acc.x += a * (x.x + y.x + v.x);
                acc.y += a * (x.y + y.y + v.y);
                acc.z += a * (x.z + y.z + v.z);
                acc.w += a * (x.w + y.w + v.w);
            }
        }
        sRed[msub][qd] = acc;
        __syncthreads();
        if (msub == 0) {
            float4 o = sRed[0][qd];
            #pragma unroll
            for (int r = 1; r < 8; ++r) {
                const float4 rv = sRed[r][qd];
                o.x += rv.x; o.y += rv.y; o.z += rv.z; o.w += rv.w;
            }
            out[(size_t)(b * Ln + l) * 64 + qd] = o;
        }
        __syncthreads();
    }
}

// ---------------------------------------------------------------------------
extern "C" void kernel_launch(void* const* d_in, const int* in_sizes, int n_in,
                              void* d_out, int out_size)
{
    const float4* queries = (const float4*)d_in[0];
    const float4* keys    = (const float4*)d_in[1];
    const float4* tK      = (const float4*)d_in[2];
    const float4* tV      = (const float4*)d_in[3];
    const float4* dK      = (const float4*)d_in[4];
    const float4* dV      = (const float4*)d_in[5];
    const float4* apK     = (const float4*)d_in[6];
    const float4* apV     = (const float4*)d_in[7];
    const float4* Qw      = (const float4*)d_in[8];
    const float* Qb       = (const float*)d_in[9];
    const float4* Kw      = (const float4*)d_in[10];
    const float* Kb       = (const float*)d_in[11];
    const float4* Vw      = (const float4*)d_in[12];
    const float* Vb       = (const float*)d_in[13];
    const unsigned char* time_mask = (const unsigned char*)d_in[14];

    proj_sgemm<<<dim3(13, 4, 3), 256>>>(queries, keys, apK, apV,
                                        Qw, Qb, Kw, Kb, Vw, Vb);
    attn_kernel<<<(Bn * Ln) / 2, 512>>>(tK, tV, dK, dV, time_mask, (float4*)d_out);
}

// round 7
// speedup vs baseline: 1.3237x; 1.3237x over previous
#include <cuda_runtime.h>

#define Bn 4
#define Ln 200
#define Hn 256
#define NHn 4
#define HSn 64
#define Mrows (Bn * Ln)        // 800

__device__ float4 g_Q4 [Bn * Ln * (Hn / 4)];
__device__ float4 g_Kc4[Bn * Ln * (Hn / 4)];
__device__ float4 g_Vc4[Bn * Ln * (Hn / 4)];

// ---------------------------------------------------------------------------
// Strip projection GEMM: exactly 148 CTAs (one per SM).
//   CTAs [0,49)   -> Q  = queries @ Qw^T + Qb
//   CTAs [49,98)  -> Kc = keys    @ Kw^T + Kb + abs_pos_K
//   CTAs [98,148) -> Vc = keys    @ Vw^T + Vb + abs_pos_V
// Each CTA computes a 16-17 row x 256 col strip. 256 thr = 4 ty x 64 tx,
// each thread 5 rows x 4 cols (rows clamped; junk discarded at store).
// Per kk: 1 LDS.128 (w) + 5 broadcast LDS (a) + 20 FMA -> FMA-bound.
// ---------------------------------------------------------------------------
#define WPITCH 260
#define XROWS 20

__global__ __launch_bounds__(256)
void proj_strip(const float4* __restrict__ queries,
                const float4* __restrict__ keys,
                const float4* __restrict__ apK4,
                const float4* __restrict__ apV4,
                const float4* __restrict__ Qw4, const float* __restrict__ Qb,
                const float4* __restrict__ Kw4, const float* __restrict__ Kb,
                const float4* __restrict__ Vw4, const float* __restrict__ Vb)
{
    __shared__ float xs[16][XROWS];      // xs[kk][row]
    __shared__ float ws[16][WPITCH];     // ws[kk][col]

    const int bx = blockIdx.x;
    const int z  = (bx < 49) ? 0 : (bx < 98) ? 1 : 2;
    const int li = bx - ((z == 0) ? 0 : (z == 1) ? 49 : 98);
    const int nC = (z == 2) ? 50 : 49;

    const int r0  = (Mrows * li) / nC;
    const int r1  = (Mrows * (li + 1)) / nC;
    const int cnt = r1 - r0;                       // 16 or 17

    const float4* __restrict__ X  = (z == 0) ? queries : keys;
    const float4* __restrict__ W  = (z == 0) ? Qw4 : (z == 1) ? Kw4 : Vw4;
    const float*  __restrict__ Bv = (z == 0) ? Qb : (z == 1) ? Kb : Vb;

    const int t  = threadIdx.x;
    const int tx = t & 63;
    const int ty = t >> 6;

    int rowIdx[5];
    #pragma unroll
    for (int j = 0; j < 5; ++j) {
        int rr = ty + 4 * j;
        rowIdx[j] = (rr < cnt) ? rr : (cnt - 1);
    }

    float acc[5][4];
    #pragma unroll
    for (int j = 0; j < 5; ++j)
        #pragma unroll
        for (int c = 0; c < 4; ++c) acc[j][c] = 0.f;

    // staging indices
    const bool doX = (t < 4 * cnt);
    const int  xrow = t >> 2, xq = t & 3;
    int wcol[4], wq[4];
    #pragma unroll
    for (int u = 0; u < 4; ++u) {
        const int e = t + 256 * u;                 // 0..1023
        wcol[u] = e >> 2;
        wq[u]   = e & 3;
    }

    // initial prefetch (chunk 0)
    float4 xr = make_float4(0.f, 0.f, 0.f, 0.f);
    if (doX) xr = X[(r0 + xrow) * 64 + xq];
    float4 wr[4];
    #pragma unroll
    for (int u = 0; u < 4; ++u) wr[u] = W[wcol[u] * 64 + wq[u]];

    for (int k0 = 0; k0 < Hn; k0 += 16) {
        // stage current chunk
        if (doX) {
            xs[xq * 4 + 0][xrow] = xr.x;
            xs[xq * 4 + 1][xrow] = xr.y;
            xs[xq * 4 + 2][xrow] = xr.z;
            xs[xq * 4 + 3][xrow] = xr.w;
        }
        #pragma unroll
        for (int u = 0; u < 4; ++u) {
            ws[wq[u] * 4 + 0][wcol[u]] = wr[u].x;
            ws[wq[u] * 4 + 1][wcol[u]] = wr[u].y;
            ws[wq[u] * 4 + 2][wcol[u]] = wr[u].z;
            ws[wq[u] * 4 + 3][wcol[u]] = wr[u].w;
        }
        __syncthreads();

        // prefetch next chunk while computing
        if (k0 + 16 < Hn) {
            const int kq = (k0 + 16) >> 2;
            if (doX) xr = X[(r0 + xrow) * 64 + kq + xq];
            #pragma unroll
            for (int u = 0; u < 4; ++u) wr[u] = W[wcol[u] * 64 + kq + wq[u]];
        }

        #pragma unroll
        for (int kk = 0; kk < 16; ++kk) {
            const float4 w = *reinterpret_cast<const float4*>(&ws[kk][tx * 4]);
            #pragma unroll
            for (int j = 0; j < 5; ++j) {
                const float a = xs[kk][rowIdx[j]];
                acc[j][0] += a * w.x;
                acc[j][1] += a * w.y;
                acc[j][2] += a * w.z;
                acc[j][3] += a * w.w;
            }
        }
        __syncthreads();
    }

    // epilogue: bias (+abs_pos), float4 stores; junk rows discarded
    const float4 bias = reinterpret_cast<const float4*>(Bv)[tx];
    float4* __restrict__ dst = (z == 0) ? g_Q4 : (z == 1) ? g_Kc4 : g_Vc4;
    const float4* __restrict__ ap = (z == 1) ? apK4 : apV4;

    #pragma unroll
    for (int j = 0; j < 5; ++j) {
        const int rr = ty + 4 * j;
        if (rr < cnt) {
            const int row = r0 + rr;
            float4 o;
            o.x = acc[j][0] + bias.x;
            o.y = acc[j][1] + bias.y;
            o.z = acc[j][2] + bias.z;
            o.w = acc[j][3] + bias.w;
            if (z != 0) {
                const float4 pa = ap[row * 64 + tx];
                o.x += pa.x; o.y += pa.y; o.z += pa.z; o.w += pa.w;
            }
            dst[row * 64 + tx] = o;
        }
    }
}

// ---------------------------------------------------------------------------
// Attention (R5 exact — measured 57.1us @ 74.4% DRAM).
// One CTA per (b, row-pair): pairing l and L-1-l -> constant per-CTA work.
// 512 threads = 8 key-rows in flight x 64 float4 lanes.
// ---------------------------------------------------------------------------
__global__ __launch_bounds__(512)
void attn_kernel(const float4* __restrict__ tK, const float4* __restrict__ tV,
                 const float4* __restrict__ dK, const float4* __restrict__ dV,
                 const unsigned char* __restrict__ time_mask,
                 float4* __restrict__ out)
{
    const int bx = blockIdx.x;               // 0..399
    const int b  = bx & (Bn - 1);
    const int p  = bx >> 2;                  // 0..99
    const int t    = threadIdx.x;
    const int msub = t >> 6;                 // 0..7
    const int qd   = t & 63;
    const int head = qd >> 4;

    __shared__ float  sW[NHn][Ln];
    __shared__ float4 sRed[8][64];
    __shared__ float  qsh[Hn];

    const float4* __restrict__ Kc4 = g_Kc4;
    const float4* __restrict__ Vc4 = g_Vc4;
    const float*  __restrict__ gQ  = (const float*)g_Q4;

    #pragma unroll 1
    for (int rr = 0; rr < 2; ++rr) {
        const int l = rr ? p : (Ln - 1 - p);   // heavy row first

        if (t < Hn) qsh[t] = gQ[(size_t)(b * Ln + l) * Hn + t];
        __syncthreads();
        const float4 qv = *reinterpret_cast<const float4*>(&qsh[qd * 4]);

        const bool tm   = time_mask[b * Ln + l] != 0;
        const int  mEnd = tm ? Ln : (l + 1);
        const size_t rowBase = ((size_t)(b * Ln + l)) * Ln;

        if (!tm) {
            #pragma unroll 2
            for (int m0 = 0; m0 < mEnd; m0 += 8) {
                const int m = m0 + msub;
                float s = 0.f;
                if (m < mEnd) {
                    const size_t off = (rowBase + (size_t)m) * 64 + qd;
                    const float4 a = tK[off];
                    const float4 c = dK[off];
                    const float4 k = Kc4[(size_t)(b * Ln + m) * 64 + qd];
                    s = qv.x * (a.x + c.x + k.x) + qv.y * (a.y + c.y + k.y)
                      + qv.z * (a.z + c.z + k.z) + qv.w * (a.w + c.w + k.w);
                }
                s += __shfl_xor_sync(0xffffffffu, s, 8);
                s += __shfl_xor_sync(0xffffffffu, s, 4);
                s += __shfl_xor_sync(0xffffffffu, s, 2);
                s += __shfl_xor_sync(0xffffffffu, s, 1);
                if (m < mEnd && (qd & 15) == 0)
                    sW[head][m] = s;
            }
            __syncthreads();

            if (t < 128) {
                const int h    = t >> 5;
                const int lane = t & 31;
                float mx = -3.4e38f;
                for (int m = lane; m < mEnd; m += 32) mx = fmaxf(mx, sW[h][m]);
                #pragma unroll
                for (int o = 16; o; o >>= 1) mx = fmaxf(mx, __shfl_xor_sync(0xffffffffu, mx, o));
                float sum = 0.f;
                for (int m = lane; m < mEnd; m += 32) {
                    const float e = __expf(0.125f * (sW[h][m] - mx));  // 1/sqrt(64)
                    sW[h][m] = e;
                    sum += e;
                }
                #pragma unroll
                for (int o = 16; o; o >>= 1) sum += __shfl_xor_sync(0xffffffffu, sum, o);
                const float inv = 1.f / sum;
                for (int m = lane; m < mEnd; m += 32) sW[h][m] *= inv;
            }
        } else {
            const float u = 1.f / (float)Ln;
            for (int m = t; m < Ln; m += 512) {
                sW[0][m] = u; sW[1][m] = u; sW[2][m] = u; sW[3][m] = u;
            }
        }
        __syncthreads();

        float4 acc = make_float4(0.f, 0.f, 0.f, 0.f);
        #pragma unroll 2
        for (int m0 = 0; m0 < mEnd; m0 += 8) {
            const int m = m0 + msub;
            if (m < mEnd) {
                const float  a   = sW[head][m];
                const size_t off = (rowBase + (size_t)m) * 64 + qd;
                const float4 x = tV[off];
                const float4 y = dV[off];
                const float4 v = Vc4[(size_t)(b * Ln + m) * 64 + qd];
                acc.x += a * (x.x + y.x + v.x);
                acc.y += a * (x.y + y.y + v.y);
                acc.z += a * (x.z + y.z + v.z);
                acc.w += a * (x.w + y.w + v.w);
            }
        }
        sRed[msub][qd] = acc;
        __syncthreads();
        if (msub == 0) {
            float4 o = sRed[0][qd];
            #pragma unroll
            for (int r = 1; r < 8; ++r) {
                const float4 rv = sRed[r][qd];
                o.x += rv.x; o.y += rv.y; o.z += rv.z; o.w += rv.w;
            }
            out[(size_t)(b * Ln + l) * 64 + qd] = o;
        }
        __syncthreads();
    }
}

// ---------------------------------------------------------------------------
extern "C" void kernel_launch(void* const* d_in, const int* in_sizes, int n_in,
                              void* d_out, int out_size)
{
    const float4* queries = (const float4*)d_in[0];
    const float4* keys    = (const float4*)d_in[1];
    const float4* tK      = (const float4*)d_in[2];
    const float4* tV      = (const float4*)d_in[3];
    const float4* dK      = (const float4*)d_in[4];
    const float4* dV      = (const float4*)d_in[5];
    const float4* apK     = (const float4*)d_in[6];
    const float4* apV     = (const float4*)d_in[7];
    const float4* Qw      = (const float4*)d_in[8];
    const float* Qb       = (const float*)d_in[9];
    const float4* Kw      = (const float4*)d_in[10];
    const float* Kb       = (const float*)d_in[11];
    const float4* Vw      = (const float4*)d_in[12];
    const float* Vb       = (const float*)d_in[13];
    const unsigned char* time_mask = (const unsigned char*)d_in[14];

    proj_strip<<<148, 256>>>(queries, keys, apK, apV,
                             Qw, Qb, Kw, Kb, Vw, Vb);
    attn_kernel<<<(Bn * Ln) / 2, 512>>>(tK, tV, dK, dV, time_mask, (float4*)d_out);
}